// round 4
// baseline (speedup 1.0000x reference)
#include <cuda_runtime.h>
#include <cuda_bf16.h>
#include <math.h>

// Problem dims (fixed by the dataset)
#define BB  4
#define SS  2048
#define DD  512
#define HH  8
#define HD  64
#define MM  (BB*SS)          // 8192
#define BKT 16               // K tile per stage
#define LDK 24               // padded bf16 row (48B stride: conflict-free mod 128)

// Scratch (allocation-free rule: __device__ globals)
__device__ float g_q  [(size_t)MM * DD];
__device__ float g_k  [(size_t)MM * DD];
__device__ float g_v  [(size_t)MM * DD];
__device__ float g_ctx[(size_t)MM * DD];
__device__ float g_attn[(size_t)BB * HH * SS * SS];   // 536.9 MB

// ---------------------------------------------------------------------------
// bf16 split helpers:  x ~= hi + lo, |x - hi - lo| <~ 2^-18 |x|
// ---------------------------------------------------------------------------
__device__ __forceinline__ void split2(float x0, float x1, unsigned& h, unsigned& l)
{
    __nv_bfloat162 hb = __floats2bfloat162_rn(x0, x1);
    float2 hf = __bfloat1622float2(hb);
    __nv_bfloat162 lb = __floats2bfloat162_rn(x0 - hf.x, x1 - hf.y);
    h = *reinterpret_cast<unsigned*>(&hb);
    l = *reinterpret_cast<unsigned*>(&lb);
}
__device__ __forceinline__ void split1(float x, __nv_bfloat16& h, __nv_bfloat16& l)
{
    h = __float2bfloat16_rn(x);
    l = __float2bfloat16_rn(x - __bfloat162float(h));
}

__device__ __forceinline__ void mma16816(float c[4],
    unsigned a0, unsigned a1, unsigned a2, unsigned a3,
    unsigned b0, unsigned b1)
{
    asm volatile(
        "mma.sync.aligned.m16n8k16.row.col.f32.bf16.bf16.f32 "
        "{%0,%1,%2,%3},{%4,%5,%6,%7},{%8,%9},{%0,%1,%2,%3};"
        : "+f"(c[0]), "+f"(c[1]), "+f"(c[2]), "+f"(c[3])
        : "r"(a0), "r"(a1), "r"(a2), "r"(a3), "r"(b0), "r"(b1));
}

// ---------------------------------------------------------------------------
// Unified tensor-core GEMM (bf16x3 split, fp32 accumulate), double-buffered:
//   C[M,N] = scale * A @ op(B) + bias
// A row-major [M,K] (lda), B either [K,N] (NN) or [N,K] (NT, TRANS_B).
// Batched over blockIdx.z = b*8+h. 256 threads = 8 warps (2 x 4).
// One __syncthreads per K-step; smem stores go to the idle stage.
// ---------------------------------------------------------------------------
template<int BM, int BN, bool TRANS_B, bool HAS_BIAS>
__global__ void __launch_bounds__(256)
mma_gemm(const float* __restrict__ A, int lda, long long sAb, long long sAh,
         const float* __restrict__ B, int ldb, long long sBb, long long sBh,
         const float* __restrict__ bias,
         float* __restrict__ C, int ldc, long long sCb, long long sCh,
         int K, float scale)
{
    constexpr int WM  = 64;                      // warp tile M
    constexpr int WN  = BN / 4;                  // warp tile N (32 or 16)
    constexpr int MT  = WM / 16;                 // 4
    constexpr int NT_ = WN / 8;                  // 4 or 2
    constexpr int A_V = BM * BKT / 4 / 256;      // 2
    constexpr int B_V = BN * BKT / 4 / 256;      // 2 or 1

    __shared__ __nv_bfloat16 Ah[2][BM][LDK], Al[2][BM][LDK];
    __shared__ __nv_bfloat16 Bh[2][BN][LDK], Bl[2][BN][LDK];

    const int z = blockIdx.z;
    const int b = z >> 3, h = z & 7;
    A += (long long)b * sAb + (long long)h * sAh;
    B += (long long)b * sBb + (long long)h * sBh;
    C += (long long)b * sCb + (long long)h * sCh;

    const int tid   = threadIdx.x;
    const int warp  = tid >> 5;
    const int lane  = tid & 31;
    const int g     = lane >> 2;       // groupID
    const int tq    = lane & 3;        // thread-in-quad
    const int warpM = warp >> 2;       // 0..1
    const int warpN = warp & 3;        // 0..3
    const int m0    = blockIdx.y * BM;
    const int n0    = blockIdx.x * BN;

    float acc[MT][NT_][4] = {};
    float4 pa[A_V], pb[B_V];

    // ---- gmem -> regs ----
    auto load_a = [&](int kt) {
        #pragma unroll
        for (int j = 0; j < A_V; j++) {
            int idx = tid + j * 256;
            int r = idx >> 2;           // 4 vecs per 16-wide row
            int c = (idx & 3) << 2;
            pa[j] = *(const float4*)&A[(size_t)(m0 + r) * lda + kt + c];
        }
    };
    auto load_b = [&](int kt) {
        if (TRANS_B) {
            #pragma unroll
            for (int j = 0; j < B_V; j++) {
                int idx = tid + j * 256;
                int r = idx >> 2;
                int c = (idx & 3) << 2;
                pb[j] = *(const float4*)&B[(size_t)(n0 + r) * ldb + kt + c];
            }
        } else {
            #pragma unroll
            for (int j = 0; j < B_V; j++) {
                int idx = tid + j * 256;
                int r = idx / (BN / 4);
                int c = (idx % (BN / 4)) << 2;
                pb[j] = *(const float4*)&B[(size_t)(kt + r) * ldb + n0 + c];
            }
        }
    };
    // ---- regs -> smem stage s (with bf16 hi/lo split) ----
    auto store_tiles = [&](int s) {
        #pragma unroll
        for (int j = 0; j < A_V; j++) {
            int idx = tid + j * 256;
            int r = idx >> 2;
            int c = (idx & 3) << 2;
            unsigned h01, l01, h23, l23;
            split2(pa[j].x, pa[j].y, h01, l01);
            split2(pa[j].z, pa[j].w, h23, l23);
            *(unsigned*)&Ah[s][r][c]     = h01;
            *(unsigned*)&Ah[s][r][c + 2] = h23;
            *(unsigned*)&Al[s][r][c]     = l01;
            *(unsigned*)&Al[s][r][c + 2] = l23;
        }
        if (TRANS_B) {
            #pragma unroll
            for (int j = 0; j < B_V; j++) {
                int idx = tid + j * 256;
                int r = idx >> 2;
                int c = (idx & 3) << 2;
                unsigned h01, l01, h23, l23;
                split2(pb[j].x, pb[j].y, h01, l01);
                split2(pb[j].z, pb[j].w, h23, l23);
                *(unsigned*)&Bh[s][r][c]     = h01;
                *(unsigned*)&Bh[s][r][c + 2] = h23;
                *(unsigned*)&Bl[s][r][c]     = l01;
                *(unsigned*)&Bl[s][r][c + 2] = l23;
            }
        } else {
            #pragma unroll
            for (int j = 0; j < B_V; j++) {
                int idx = tid + j * 256;
                int r = idx / (BN / 4);
                int c = (idx % (BN / 4)) << 2;
                float v[4] = { pb[j].x, pb[j].y, pb[j].z, pb[j].w };
                #pragma unroll
                for (int q = 0; q < 4; q++) {
                    __nv_bfloat16 hh, ll;
                    split1(v[q], hh, ll);
                    Bh[s][c + q][r] = hh;
                    Bl[s][c + q][r] = ll;
                }
            }
        }
    };

    const int NKT = K / BKT;

    // prolog: tile0 -> stage0; tile1 -> regs
    load_a(0); load_b(0);
    store_tiles(0);
    if (NKT > 1) { load_a(BKT); load_b(BKT); }
    __syncthreads();

    for (int kt = 0; kt < NKT; kt++) {
        const int buf = kt & 1;
        if (kt + 1 < NKT) store_tiles(buf ^ 1);                    // regs hold tile kt+1
        if (kt + 2 < NKT) { load_a((kt + 2) * BKT); load_b((kt + 2) * BKT); }

        // fragment loads (conflict-free: 48B row stride)
        unsigned afh[MT][4], afl[MT][4], bfh[NT_][2], bfl[NT_][2];
        #pragma unroll
        for (int mt = 0; mt < MT; mt++) {
            int r0 = warpM * WM + mt * 16 + g;
            afh[mt][0] = *(unsigned*)&Ah[buf][r0][2 * tq];
            afh[mt][1] = *(unsigned*)&Ah[buf][r0 + 8][2 * tq];
            afh[mt][2] = *(unsigned*)&Ah[buf][r0][2 * tq + 8];
            afh[mt][3] = *(unsigned*)&Ah[buf][r0 + 8][2 * tq + 8];
            afl[mt][0] = *(unsigned*)&Al[buf][r0][2 * tq];
            afl[mt][1] = *(unsigned*)&Al[buf][r0 + 8][2 * tq];
            afl[mt][2] = *(unsigned*)&Al[buf][r0][2 * tq + 8];
            afl[mt][3] = *(unsigned*)&Al[buf][r0 + 8][2 * tq + 8];
        }
        #pragma unroll
        for (int nt = 0; nt < NT_; nt++) {
            int c0 = warpN * WN + nt * 8 + g;
            bfh[nt][0] = *(unsigned*)&Bh[buf][c0][2 * tq];
            bfh[nt][1] = *(unsigned*)&Bh[buf][c0][2 * tq + 8];
            bfl[nt][0] = *(unsigned*)&Bl[buf][c0][2 * tq];
            bfl[nt][1] = *(unsigned*)&Bl[buf][c0][2 * tq + 8];
        }

        #pragma unroll
        for (int mt = 0; mt < MT; mt++)
            #pragma unroll
            for (int nt = 0; nt < NT_; nt++) {
                mma16816(acc[mt][nt], afh[mt][0], afh[mt][1], afh[mt][2], afh[mt][3],
                         bfh[nt][0], bfh[nt][1]);
                mma16816(acc[mt][nt], afh[mt][0], afh[mt][1], afh[mt][2], afh[mt][3],
                         bfl[nt][0], bfl[nt][1]);
                mma16816(acc[mt][nt], afl[mt][0], afl[mt][1], afl[mt][2], afl[mt][3],
                         bfh[nt][0], bfh[nt][1]);
            }

        __syncthreads();
    }

    // epilogue
    #pragma unroll
    for (int mt = 0; mt < MT; mt++) {
        int r0 = m0 + warpM * WM + mt * 16 + g;
        #pragma unroll
        for (int nt = 0; nt < NT_; nt++) {
            int c = n0 + warpN * WN + nt * 8 + 2 * tq;
            float bx = 0.f, by = 0.f;
            if (HAS_BIAS) { bx = bias[c]; by = bias[c + 1]; }
            float2 v0, v1;
            v0.x = acc[mt][nt][0] * scale + bx;
            v0.y = acc[mt][nt][1] * scale + by;
            v1.x = acc[mt][nt][2] * scale + bx;
            v1.y = acc[mt][nt][3] * scale + by;
            *(float2*)&C[(size_t)r0 * ldc + c]       = v0;
            *(float2*)&C[(size_t)(r0 + 8) * ldc + c] = v1;
        }
    }
}

// ---------------------------------------------------------------------------
// Softmax over k + head-mean.  One 512-thread block per (b, q).
// Each thread owns exactly one float4 of the 2048-wide row per head.
// In-place probs; writes avg_attn[b,q,:].
// ---------------------------------------------------------------------------
__device__ __forceinline__ float blk_reduce512(float v, bool is_max)
{
    __shared__ float sm[16];
    #pragma unroll
    for (int o = 16; o > 0; o >>= 1) {
        float w = __shfl_xor_sync(0xffffffffu, v, o);
        v = is_max ? fmaxf(v, w) : (v + w);
    }
    if ((threadIdx.x & 31) == 0) sm[threadIdx.x >> 5] = v;
    __syncthreads();
    float r = sm[0];
    #pragma unroll
    for (int i = 1; i < 16; i++) r = is_max ? fmaxf(r, sm[i]) : (r + sm[i]);
    __syncthreads();
    return r;
}

__global__ void __launch_bounds__(512)
softmax_avg_kernel(float* __restrict__ avg_out)
{
    const int bq  = blockIdx.x;            // 0 .. B*S-1
    const int b   = bq / SS;
    const int q   = bq % SS;
    const int tid = threadIdx.x;

    float4 av = make_float4(0.f, 0.f, 0.f, 0.f);

    for (int h = 0; h < HH; h++) {
        float* row = g_attn + (((size_t)(b*HH + h)) * SS + q) * SS;
        float4 v = *(float4*)&row[tid * 4];
        float m = fmaxf(fmaxf(v.x, v.y), fmaxf(v.z, v.w));
        m = blk_reduce512(m, true);
        v.x = __expf(v.x - m);
        v.y = __expf(v.y - m);
        v.z = __expf(v.z - m);
        v.w = __expf(v.w - m);
        float s = (v.x + v.y) + (v.z + v.w);
        s = blk_reduce512(s, false);
        float inv = 1.f / s;
        v.x *= inv; v.y *= inv; v.z *= inv; v.w *= inv;
        *(float4*)&row[tid * 4] = v;
        av.x += v.x * (1.0f / HH);
        av.y += v.y * (1.0f / HH);
        av.z += v.z * (1.0f / HH);
        av.w += v.w * (1.0f / HH);
    }
    float* arow = avg_out + ((size_t)b * SS + q) * SS;
    *(float4*)&arow[tid * 4] = av;
}

// ---------------------------------------------------------------------------
extern "C" void kernel_launch(void* const* d_in, const int* in_sizes, int n_in,
                              void* d_out, int out_size)
{
    const float* x  = (const float*)d_in[0];
    const float* Wq = (const float*)d_in[1];
    const float* bq = (const float*)d_in[2];
    const float* Wk = (const float*)d_in[3];
    const float* bk = (const float*)d_in[4];
    const float* Wv = (const float*)d_in[5];
    const float* bv = (const float*)d_in[6];
    const float* Wo = (const float*)d_in[7];
    const float* bo = (const float*)d_in[8];

    float* out = (float*)d_out;                       // [B,S,D]
    float* avg = out + (size_t)BB * SS * DD;          // [B,S,S]

    float *pq, *pk, *pv, *pctx, *pattn;
    cudaGetSymbolAddress((void**)&pq,    g_q);
    cudaGetSymbolAddress((void**)&pk,    g_k);
    cudaGetSymbolAddress((void**)&pv,    g_v);
    cudaGetSymbolAddress((void**)&pctx,  g_ctx);
    cudaGetSymbolAddress((void**)&pattn, g_attn);

    dim3 blk(256);
    const long long SD = (long long)SS * DD;
    const long long S2 = (long long)SS * SS;

    // 1) QKV projections: [8192,512] = x @ W + b   (NN, z=1)
    dim3 g1(DD/128, MM/128, 1);
    mma_gemm<128,128,false,true><<<g1, blk>>>(x, DD, 0, 0, Wq, DD, 0, 0, bq, pq,  DD, 0, 0, DD, 1.f);
    mma_gemm<128,128,false,true><<<g1, blk>>>(x, DD, 0, 0, Wk, DD, 0, 0, bk, pk,  DD, 0, 0, DD, 1.f);
    mma_gemm<128,128,false,true><<<g1, blk>>>(x, DD, 0, 0, Wv, DD, 0, 0, bv, pv,  DD, 0, 0, DD, 1.f);

    // 2) scores: P = scale * Q K^T  (NT, batched z = b*8+h)
    dim3 g2(SS/128, SS/128, BB*HH);
    mma_gemm<128,128,true,false><<<g2, blk>>>(pq, DD, SD, HD, pk, DD, SD, HD, nullptr,
                                              pattn, SS, 8*S2, S2, HD, 0.125f);

    // 3) softmax over k + head-mean -> avg_attn (probs in place)
    softmax_avg_kernel<<<BB*SS, 512>>>(avg);

    // 4) ctx = P @ V  (NN, batched)
    dim3 g3(1, SS/128, BB*HH);
    mma_gemm<128,64,false,false><<<g3, blk>>>(pattn, SS, 8*S2, S2, pv, DD, SD, HD, nullptr,
                                              pctx, DD, SD, HD, SS, 1.f);

    // 5) out = ctx @ Wo + bo
    mma_gemm<128,128,false,true><<<g1, blk>>>(pctx, DD, 0, 0, Wo, DD, 0, 0, bo, out, DD, 0, 0, DD, 1.f);
}

// round 5
// speedup vs baseline: 1.5484x; 1.5484x over previous
#include <cuda_runtime.h>
#include <cuda_bf16.h>
#include <cuda_fp16.h>
#include <math.h>

// Problem dims (fixed by the dataset)
#define BB  4
#define SS  2048
#define DD  512
#define HH  8
#define HD  64
#define MM  (BB*SS)          // 8192
#define BKT 16               // K tile per stage (bf16x3 GEMM)
#define LDK 18               // padded bf16 row (round-3 layout)

// Scratch (allocation-free rule: __device__ globals)
__device__ float  g_q   [(size_t)MM * DD];
__device__ float  g_k   [(size_t)MM * DD];
__device__ __align__(16) __half g_vh[(size_t)MM * DD];            // fp16 V
__device__ float  g_ctx [(size_t)MM * DD];
__device__ float  g_attn[(size_t)BB * HH * SS * SS];              // fp32 scores, 537MB
__device__ __align__(16) __half g_p[(size_t)BB * HH * SS * SS];   // fp16 probs, 268MB

// ---------------------------------------------------------------------------
// bf16 split helpers:  x ~= hi + lo, |x - hi - lo| <~ 2^-18 |x|
// ---------------------------------------------------------------------------
__device__ __forceinline__ void split2(float x0, float x1, unsigned& h, unsigned& l)
{
    __nv_bfloat162 hb = __floats2bfloat162_rn(x0, x1);
    float2 hf = __bfloat1622float2(hb);
    __nv_bfloat162 lb = __floats2bfloat162_rn(x0 - hf.x, x1 - hf.y);
    h = *reinterpret_cast<unsigned*>(&hb);
    l = *reinterpret_cast<unsigned*>(&lb);
}
__device__ __forceinline__ void split1(float x, __nv_bfloat16& h, __nv_bfloat16& l)
{
    h = __float2bfloat16_rn(x);
    l = __float2bfloat16_rn(x - __bfloat162float(h));
}

__device__ __forceinline__ void mma16816(float c[4],
    unsigned a0, unsigned a1, unsigned a2, unsigned a3,
    unsigned b0, unsigned b1)
{
    asm volatile(
        "mma.sync.aligned.m16n8k16.row.col.f32.bf16.bf16.f32 "
        "{%0,%1,%2,%3},{%4,%5,%6,%7},{%8,%9},{%0,%1,%2,%3};"
        : "+f"(c[0]), "+f"(c[1]), "+f"(c[2]), "+f"(c[3])
        : "r"(a0), "r"(a1), "r"(a2), "r"(a3), "r"(b0), "r"(b1));
}
__device__ __forceinline__ void mma16816_f16(float c[4],
    unsigned a0, unsigned a1, unsigned a2, unsigned a3,
    unsigned b0, unsigned b1)
{
    asm volatile(
        "mma.sync.aligned.m16n8k16.row.col.f32.f16.f16.f32 "
        "{%0,%1,%2,%3},{%4,%5,%6,%7},{%8,%9},{%0,%1,%2,%3};"
        : "+f"(c[0]), "+f"(c[1]), "+f"(c[2]), "+f"(c[3])
        : "r"(a0), "r"(a1), "r"(a2), "r"(a3), "r"(b0), "r"(b1));
}

// ---------------------------------------------------------------------------
// Unified tensor-core GEMM (bf16x3 split, fp32 accumulate) — round-3 structure:
//   C[M,N] = scale * A @ op(B) + bias
// HALF_OUT: C stored as __half (used for V projection).
// ---------------------------------------------------------------------------
template<int BM, int BN, bool TRANS_B, bool HAS_BIAS, bool HALF_OUT>
__global__ void __launch_bounds__(256, 2)
mma_gemm(const float* __restrict__ A, int lda, long long sAb, long long sAh,
         const float* __restrict__ B, int ldb, long long sBb, long long sBh,
         const float* __restrict__ bias,
         void* __restrict__ Cv, int ldc, long long sCb, long long sCh,
         int K, float scale)
{
    constexpr int WM  = 64;
    constexpr int WN  = BN / 4;
    constexpr int MT  = WM / 16;
    constexpr int NT_ = WN / 8;
    constexpr int A_V = BM * BKT / 4 / 256;
    constexpr int B_V = BN * BKT / 4 / 256;

    __shared__ __nv_bfloat16 Ah[BM][LDK], Al[BM][LDK];
    __shared__ __nv_bfloat16 Bh[BN][LDK], Bl[BN][LDK];

    const int z = blockIdx.z;
    const int b = z >> 3, h = z & 7;
    A += (long long)b * sAb + (long long)h * sAh;
    B += (long long)b * sBb + (long long)h * sBh;

    const int tid   = threadIdx.x;
    const int warp  = tid >> 5;
    const int lane  = tid & 31;
    const int g     = lane >> 2;
    const int tq    = lane & 3;
    const int warpM = warp >> 2;
    const int warpN = warp & 3;
    const int m0    = blockIdx.y * BM;
    const int n0    = blockIdx.x * BN;

    float acc[MT][NT_][4] = {};
    float4 pa[A_V], pb[B_V];

    auto load_a = [&](int kt) {
        #pragma unroll
        for (int j = 0; j < A_V; j++) {
            int idx = tid + j * 256;
            int r = idx >> 2;
            int c = (idx & 3) << 2;
            pa[j] = *(const float4*)&A[(size_t)(m0 + r) * lda + kt + c];
        }
    };
    auto load_b = [&](int kt) {
        if (TRANS_B) {
            #pragma unroll
            for (int j = 0; j < B_V; j++) {
                int idx = tid + j * 256;
                int r = idx >> 2;
                int c = (idx & 3) << 2;
                pb[j] = *(const float4*)&B[(size_t)(n0 + r) * ldb + kt + c];
            }
        } else {
            #pragma unroll
            for (int j = 0; j < B_V; j++) {
                int idx = tid + j * 256;
                int r = idx / (BN / 4);
                int c = (idx % (BN / 4)) << 2;
                pb[j] = *(const float4*)&B[(size_t)(kt + r) * ldb + n0 + c];
            }
        }
    };
    auto store_a = [&]() {
        #pragma unroll
        for (int j = 0; j < A_V; j++) {
            int idx = tid + j * 256;
            int r = idx >> 2;
            int c = (idx & 3) << 2;
            unsigned h01, l01, h23, l23;
            split2(pa[j].x, pa[j].y, h01, l01);
            split2(pa[j].z, pa[j].w, h23, l23);
            *(unsigned*)&Ah[r][c]     = h01;
            *(unsigned*)&Ah[r][c + 2] = h23;
            *(unsigned*)&Al[r][c]     = l01;
            *(unsigned*)&Al[r][c + 2] = l23;
        }
    };
    auto store_b = [&]() {
        if (TRANS_B) {
            #pragma unroll
            for (int j = 0; j < B_V; j++) {
                int idx = tid + j * 256;
                int r = idx >> 2;
                int c = (idx & 3) << 2;
                unsigned h01, l01, h23, l23;
                split2(pb[j].x, pb[j].y, h01, l01);
                split2(pb[j].z, pb[j].w, h23, l23);
                *(unsigned*)&Bh[r][c]     = h01;
                *(unsigned*)&Bh[r][c + 2] = h23;
                *(unsigned*)&Bl[r][c]     = l01;
                *(unsigned*)&Bl[r][c + 2] = l23;
            }
        } else {
            #pragma unroll
            for (int j = 0; j < B_V; j++) {
                int idx = tid + j * 256;
                int r = idx / (BN / 4);
                int c = (idx % (BN / 4)) << 2;
                float v[4] = { pb[j].x, pb[j].y, pb[j].z, pb[j].w };
                #pragma unroll
                for (int q = 0; q < 4; q++) {
                    __nv_bfloat16 hh, ll;
                    split1(v[q], hh, ll);
                    Bh[c + q][r] = hh;
                    Bl[c + q][r] = ll;
                }
            }
        }
    };

    const int NKT = K / BKT;
    load_a(0); load_b(0);
    store_a(); store_b();
    __syncthreads();

    for (int kt = 0; kt < NKT; kt++) {
        if (kt + 1 < NKT) { load_a((kt + 1) * BKT); load_b((kt + 1) * BKT); }

        unsigned afh[MT][4], afl[MT][4], bfh[NT_][2], bfl[NT_][2];
        #pragma unroll
        for (int mt = 0; mt < MT; mt++) {
            int r0 = warpM * WM + mt * 16 + g;
            afh[mt][0] = *(unsigned*)&Ah[r0][2 * tq];
            afh[mt][1] = *(unsigned*)&Ah[r0 + 8][2 * tq];
            afh[mt][2] = *(unsigned*)&Ah[r0][2 * tq + 8];
            afh[mt][3] = *(unsigned*)&Ah[r0 + 8][2 * tq + 8];
            afl[mt][0] = *(unsigned*)&Al[r0][2 * tq];
            afl[mt][1] = *(unsigned*)&Al[r0 + 8][2 * tq];
            afl[mt][2] = *(unsigned*)&Al[r0][2 * tq + 8];
            afl[mt][3] = *(unsigned*)&Al[r0 + 8][2 * tq + 8];
        }
        #pragma unroll
        for (int nt = 0; nt < NT_; nt++) {
            int c0 = warpN * WN + nt * 8 + g;
            bfh[nt][0] = *(unsigned*)&Bh[c0][2 * tq];
            bfh[nt][1] = *(unsigned*)&Bh[c0][2 * tq + 8];
            bfl[nt][0] = *(unsigned*)&Bl[c0][2 * tq];
            bfl[nt][1] = *(unsigned*)&Bl[c0][2 * tq + 8];
        }

        #pragma unroll
        for (int mt = 0; mt < MT; mt++)
            #pragma unroll
            for (int nt = 0; nt < NT_; nt++) {
                mma16816(acc[mt][nt], afh[mt][0], afh[mt][1], afh[mt][2], afh[mt][3],
                         bfh[nt][0], bfh[nt][1]);
                mma16816(acc[mt][nt], afh[mt][0], afh[mt][1], afh[mt][2], afh[mt][3],
                         bfl[nt][0], bfl[nt][1]);
                mma16816(acc[mt][nt], afl[mt][0], afl[mt][1], afl[mt][2], afl[mt][3],
                         bfh[nt][0], bfh[nt][1]);
            }

        if (kt + 1 < NKT) {
            __syncthreads();
            store_a(); store_b();
            __syncthreads();
        }
    }

    // epilogue
    #pragma unroll
    for (int mt = 0; mt < MT; mt++) {
        int r0 = m0 + warpM * WM + mt * 16 + g;
        #pragma unroll
        for (int nt = 0; nt < NT_; nt++) {
            int c = n0 + warpN * WN + nt * 8 + 2 * tq;
            float bx = 0.f, by = 0.f;
            if (HAS_BIAS) { bx = bias[c]; by = bias[c + 1]; }
            float2 v0, v1;
            v0.x = acc[mt][nt][0] * scale + bx;
            v0.y = acc[mt][nt][1] * scale + by;
            v1.x = acc[mt][nt][2] * scale + bx;
            v1.y = acc[mt][nt][3] * scale + by;
            if (HALF_OUT) {
                __half* C = (__half*)Cv + (long long)b * sCb + (long long)h * sCh;
                *(__half2*)&C[(size_t)r0 * ldc + c]       = __floats2half2_rn(v0.x, v0.y);
                *(__half2*)&C[(size_t)(r0 + 8) * ldc + c] = __floats2half2_rn(v1.x, v1.y);
            } else {
                float* C = (float*)Cv + (long long)b * sCb + (long long)h * sCh;
                *(float2*)&C[(size_t)r0 * ldc + c]       = v0;
                *(float2*)&C[(size_t)(r0 + 8) * ldc + c] = v1;
            }
        }
    }
}

// ---------------------------------------------------------------------------
// ctx = P @ V  with fp16 inputs (single-term MMA), fp32 accum/output.
// P: g_p [z][S][S] fp16, V: g_vh [b][S][D] fp16 (slice h*HD), C: g_ctx fp32.
// Block = 128 q-rows x 64 cols, 256 threads (8 warps 2x4), BK=32 per step.
// ---------------------------------------------------------------------------
#define CBK 32
#define CLD 40   // padded halves per row (80B stride, conflict-free mod 128)
__global__ void __launch_bounds__(256, 2)
ctx_f16()
{
    constexpr int WN  = 16;
    constexpr int MT  = 4;
    constexpr int NT_ = 2;

    __shared__ __align__(16) __half Ahs[128][CLD];
    __shared__ __align__(16) __half Bhs[64][CLD];

    const int z = blockIdx.z;
    const int b = z >> 3, h = z & 7;
    const __half* P = g_p  + (size_t)z * SS * SS;
    const __half* V = g_vh + (size_t)b * SS * DD + h * HD;
    float*        C = g_ctx + (size_t)b * SS * DD + h * HD;

    const int tid   = threadIdx.x;
    const int warp  = tid >> 5;
    const int lane  = tid & 31;
    const int g     = lane >> 2;
    const int tq    = lane & 3;
    const int warpM = warp >> 2;
    const int warpN = warp & 3;
    const int m0    = blockIdx.y * 128;

    float acc[MT][NT_][4] = {};

    for (int kt = 0; kt < SS; kt += CBK) {
        // A tile: 128 x 32 halves, 2 uint4 per thread
        #pragma unroll
        for (int j = 0; j < 2; j++) {
            int idx = tid + j * 256;
            int r = idx >> 2;
            int c = (idx & 3) << 3;
            uint4 v = *(const uint4*)&P[(size_t)(m0 + r) * SS + kt + c];
            *(uint4*)&Ahs[r][c] = v;
        }
        // B tile: 32 x 64 halves (V rows), store transposed Bhs[n][k]
        {
            int k = tid >> 3;
            int c = (tid & 7) << 3;
            uint4 v = *(const uint4*)&V[(size_t)(kt + k) * DD + c];
            const __half* hv = (const __half*)&v;
            #pragma unroll
            for (int q = 0; q < 8; q++) Bhs[c + q][k] = hv[q];
        }
        __syncthreads();

        #pragma unroll
        for (int ks = 0; ks < 2; ks++) {
            const int ko = ks * 16;
            unsigned af[MT][4], bf[NT_][2];
            #pragma unroll
            for (int mt = 0; mt < MT; mt++) {
                int r0 = warpM * 64 + mt * 16 + g;
                af[mt][0] = *(unsigned*)&Ahs[r0][ko + 2 * tq];
                af[mt][1] = *(unsigned*)&Ahs[r0 + 8][ko + 2 * tq];
                af[mt][2] = *(unsigned*)&Ahs[r0][ko + 2 * tq + 8];
                af[mt][3] = *(unsigned*)&Ahs[r0 + 8][ko + 2 * tq + 8];
            }
            #pragma unroll
            for (int nt = 0; nt < NT_; nt++) {
                int c0 = warpN * WN + nt * 8 + g;
                bf[nt][0] = *(unsigned*)&Bhs[c0][ko + 2 * tq];
                bf[nt][1] = *(unsigned*)&Bhs[c0][ko + 2 * tq + 8];
            }
            #pragma unroll
            for (int mt = 0; mt < MT; mt++)
                #pragma unroll
                for (int nt = 0; nt < NT_; nt++)
                    mma16816_f16(acc[mt][nt], af[mt][0], af[mt][1], af[mt][2], af[mt][3],
                                 bf[nt][0], bf[nt][1]);
        }
        __syncthreads();
    }

    #pragma unroll
    for (int mt = 0; mt < MT; mt++) {
        int r0 = m0 + warpM * 64 + mt * 16 + g;
        #pragma unroll
        for (int nt = 0; nt < NT_; nt++) {
            int c = warpN * WN + nt * 8 + 2 * tq;
            float2 v0 = make_float2(acc[mt][nt][0], acc[mt][nt][1]);
            float2 v1 = make_float2(acc[mt][nt][2], acc[mt][nt][3]);
            *(float2*)&C[(size_t)r0 * DD + c]       = v0;
            *(float2*)&C[(size_t)(r0 + 8) * DD + c] = v1;
        }
    }
}

// ---------------------------------------------------------------------------
// Softmax over k + head-mean (round-3 structure, 256 threads).
// Reads fp32 scores, writes fp16 probs to g_p + fp32 avg_attn.
// ---------------------------------------------------------------------------
__device__ __forceinline__ float blk_reduce(float v, bool is_max)
{
    __shared__ float sm[8];
    #pragma unroll
    for (int o = 16; o > 0; o >>= 1) {
        float w = __shfl_xor_sync(0xffffffffu, v, o);
        v = is_max ? fmaxf(v, w) : (v + w);
    }
    if ((threadIdx.x & 31) == 0) sm[threadIdx.x >> 5] = v;
    __syncthreads();
    float r = sm[0];
    #pragma unroll
    for (int i = 1; i < 8; i++) r = is_max ? fmaxf(r, sm[i]) : (r + sm[i]);
    __syncthreads();
    return r;
}

__global__ void __launch_bounds__(256)
softmax_avg_kernel(float* __restrict__ avg_out)
{
    const int bq  = blockIdx.x;
    const int b   = bq / SS;
    const int q   = bq % SS;
    const int tid = threadIdx.x;
    constexpr int NPT = SS / 256;   // 8

    float av[NPT];
    #pragma unroll
    for (int j = 0; j < NPT; j++) av[j] = 0.f;

    for (int h = 0; h < HH; h++) {
        const size_t roff = (((size_t)(b*HH + h)) * SS + q) * SS;
        const float* row = g_attn + roff;
        __half* prow = g_p + roff;
        float v[NPT];
        float m = -INFINITY;
        #pragma unroll
        for (int j = 0; j < NPT; j++) {
            v[j] = row[tid + j*256];
            m = fmaxf(m, v[j]);
        }
        m = blk_reduce(m, true);
        float s = 0.f;
        #pragma unroll
        for (int j = 0; j < NPT; j++) {
            v[j] = __expf(v[j] - m);
            s += v[j];
        }
        s = blk_reduce(s, false);
        float inv = 1.f / s;
        #pragma unroll
        for (int j = 0; j < NPT; j++) {
            float p = v[j] * inv;
            prow[tid + j*256] = __float2half_rn(p);
            av[j] += p * (1.0f / HH);
        }
    }
    float* arow = avg_out + ((size_t)b * SS + q) * SS;
    #pragma unroll
    for (int j = 0; j < NPT; j++) arow[tid + j*256] = av[j];
}

// ---------------------------------------------------------------------------
extern "C" void kernel_launch(void* const* d_in, const int* in_sizes, int n_in,
                              void* d_out, int out_size)
{
    const float* x  = (const float*)d_in[0];
    const float* Wq = (const float*)d_in[1];
    const float* bq = (const float*)d_in[2];
    const float* Wk = (const float*)d_in[3];
    const float* bk = (const float*)d_in[4];
    const float* Wv = (const float*)d_in[5];
    const float* bv = (const float*)d_in[6];
    const float* Wo = (const float*)d_in[7];
    const float* bo = (const float*)d_in[8];

    float* out = (float*)d_out;                       // [B,S,D]
    float* avg = out + (size_t)BB * SS * DD;          // [B,S,S]

    float *pq, *pk, *pctx, *pattn;
    __half *pvh;
    cudaGetSymbolAddress((void**)&pq,    g_q);
    cudaGetSymbolAddress((void**)&pk,    g_k);
    cudaGetSymbolAddress((void**)&pvh,   g_vh);
    cudaGetSymbolAddress((void**)&pctx,  g_ctx);
    cudaGetSymbolAddress((void**)&pattn, g_attn);

    dim3 blk(256);
    const long long SD = (long long)SS * DD;
    const long long S2 = (long long)SS * SS;

    // 1) QKV projections: [8192,512] = x @ W + b   (NN, z=1)
    dim3 g1(DD/128, MM/128, 1);
    mma_gemm<128,128,false,true,false><<<g1, blk>>>(x, DD, 0, 0, Wq, DD, 0, 0, bq, pq,  DD, 0, 0, DD, 1.f);
    mma_gemm<128,128,false,true,false><<<g1, blk>>>(x, DD, 0, 0, Wk, DD, 0, 0, bk, pk,  DD, 0, 0, DD, 1.f);
    mma_gemm<128,128,false,true,true ><<<g1, blk>>>(x, DD, 0, 0, Wv, DD, 0, 0, bv, pvh, DD, 0, 0, DD, 1.f);

    // 2) scores: P = scale * Q K^T  (NT, batched z = b*8+h)
    dim3 g2(SS/128, SS/128, BB*HH);
    mma_gemm<128,128,true,false,false><<<g2, blk>>>(pq, DD, SD, HD, pk, DD, SD, HD, nullptr,
                                                    pattn, SS, 8*S2, S2, HD, 0.125f);

    // 3) softmax over k + head-mean -> fp16 probs + avg_attn
    softmax_avg_kernel<<<BB*SS, 256>>>(avg);

    // 4) ctx = P @ V  (fp16 MMA, batched)
    dim3 g3(1, SS/128, BB*HH);
    ctx_f16<<<g3, blk>>>();

    // 5) out = ctx @ Wo + bo
    mma_gemm<128,128,false,true,false><<<g1, blk>>>(pctx, DD, 0, 0, Wo, DD, 0, 0, bo, out, DD, 0, 0, DD, 1.f);
}